// round 4
// baseline (speedup 1.0000x reference)
#include <cuda_runtime.h>
#include <cstdint>

#define NN 50000
#define EE 800000
#define DD 96
#define FF 128

// ---------------- scratch (static device globals; no allocs) ----------------
__device__ __align__(16) float g_hA[NN * DD];
__device__ __align__(16) float g_hB[NN * DD];
__device__ __align__(16) float g_a0[NN * DD];
__device__ __align__(16) float g_a1[NN * DD];
__device__ __align__(16) float g_WfT[FF * DD];
__device__ int g_deg[2 * NN];
__device__ int g_cur[2 * NN];
__device__ int g_rowptr[2 * NN + 1];
__device__ int g_col[EE];

// ---------------- prep: zero deg + transpose Wf ----------------
__global__ void k_prep(const float* __restrict__ Wf, float* __restrict__ WfT,
                       int* __restrict__ deg, int N2) {
    int i = blockIdx.x * blockDim.x + threadIdx.x;
    if (i < N2) deg[i] = 0;
    if (i < DD * FF) {           // Wf [d][k] row-major -> WfT [k][d]
        int d = i >> 7, k = i & 127;
        WfT[k * DD + d] = Wf[i];
    }
}

// ---------------- CSR build ----------------
__global__ void k_hist(const int* __restrict__ ei, const float* __restrict__ attr,
                       int* __restrict__ deg, int E) {
    int e = (blockIdx.x * blockDim.x + threadIdx.x) * 2;
    if (e >= E) return;
    int2 d2 = *(const int2*)(ei + E + e);
    float4 a4 = *(const float4*)(attr + 2 * e);
    atomicAdd(&deg[2 * d2.x + (a4.y > a4.x ? 1 : 0)], 1);
    if (e + 1 < E)
        atomicAdd(&deg[2 * d2.y + (a4.w > a4.z ? 1 : 0)], 1);
}

__global__ void k_scan(const int* __restrict__ deg, int* __restrict__ rowptr,
                       int* __restrict__ cur, int N2) {
    __shared__ int part[1024];
    int tid = threadIdx.x;
    const int CH = (N2 + 1023) / 1024;
    int start = tid * CH;
    int end = start + CH; if (end > N2) end = N2; if (start > N2) start = N2;
    int s = 0;
    for (int i = start; i < end; i++) s += deg[i];
    part[tid] = s;
    __syncthreads();
    for (int off = 1; off < 1024; off <<= 1) {
        int v = (tid >= off) ? part[tid - off] : 0;
        __syncthreads();
        part[tid] += v;
        __syncthreads();
    }
    int excl = (tid == 0) ? 0 : part[tid - 1];
    for (int i = start; i < end; i++) {
        rowptr[i] = excl; cur[i] = excl; excl += deg[i];
    }
    if (tid == 1023) rowptr[N2] = part[1023];
}

__global__ void k_fill(const int* __restrict__ ei, const float* __restrict__ attr,
                       int* __restrict__ cur, int* __restrict__ col, int E) {
    int e = (blockIdx.x * blockDim.x + threadIdx.x) * 2;
    if (e >= E) return;
    int2 s2 = *(const int2*)(ei + e);
    int2 d2 = *(const int2*)(ei + E + e);
    float4 a4 = *(const float4*)(attr + 2 * e);
    {
        int seg = 2 * d2.x + (a4.y > a4.x ? 1 : 0);
        col[atomicAdd(&cur[seg], 1)] = s2.x;
    }
    if (e + 1 < E) {
        int seg = 2 * d2.y + (a4.w > a4.z ? 1 : 0);
        col[atomicAdd(&cur[seg], 1)] = s2.y;
    }
}

// ---------------- aggregation: a_r[n] = mean over segment of h[src] ----------------
__device__ __forceinline__ void seg_mean(const float* __restrict__ h,
                                         const int* __restrict__ col,
                                         int e0, int e1, int lane,
                                         float* __restrict__ out) {
    float s0 = 0.f, s1 = 0.f, s2 = 0.f;
    int e = e0;
    for (; e + 3 < e1; e += 4) {
        const float* p0 = h + (size_t)__ldg(&col[e])     * DD;
        const float* p1 = h + (size_t)__ldg(&col[e + 1]) * DD;
        const float* p2 = h + (size_t)__ldg(&col[e + 2]) * DD;
        const float* p3 = h + (size_t)__ldg(&col[e + 3]) * DD;
        float v00 = __ldg(p0 + lane),      v01 = __ldg(p1 + lane),      v02 = __ldg(p2 + lane),      v03 = __ldg(p3 + lane);
        float v10 = __ldg(p0 + lane + 32), v11 = __ldg(p1 + lane + 32), v12 = __ldg(p2 + lane + 32), v13 = __ldg(p3 + lane + 32);
        float v20 = __ldg(p0 + lane + 64), v21 = __ldg(p1 + lane + 64), v22 = __ldg(p2 + lane + 64), v23 = __ldg(p3 + lane + 64);
        s0 += (v00 + v01) + (v02 + v03);
        s1 += (v10 + v11) + (v12 + v13);
        s2 += (v20 + v21) + (v22 + v23);
    }
    for (; e < e1; e++) {
        const float* p = h + (size_t)__ldg(&col[e]) * DD;
        s0 += __ldg(p + lane);
        s1 += __ldg(p + lane + 32);
        s2 += __ldg(p + lane + 64);
    }
    float inv = 1.f / fmaxf((float)(e1 - e0), 1.f);
    out[lane]      = s0 * inv;
    out[lane + 32] = s1 * inv;
    out[lane + 64] = s2 * inv;
}

__global__ void k_agg(const float* __restrict__ h, const int* __restrict__ rowptr,
                      const int* __restrict__ col, float* __restrict__ a0,
                      float* __restrict__ a1, int N) {
    int warpi = (blockIdx.x * blockDim.x + threadIdx.x) >> 5;
    int lane = threadIdx.x & 31;
    if (warpi >= N) return;
    int n = warpi;
    int e00 = __ldg(&rowptr[2 * n]);
    int e01 = __ldg(&rowptr[2 * n + 1]);
    int e11 = __ldg(&rowptr[2 * n + 2]);
    seg_mean(h, col, e00, e01, lane, a0 + (size_t)n * DD);
    seg_mean(h, col, e01, e11, lane, a1 + (size_t)n * DD);
}

// ---------------- tf32 MMA helpers ----------------
__device__ __forceinline__ uint32_t f2tf(float f) {
    uint32_t u; asm("cvt.rna.tf32.f32 %0, %1;" : "=r"(u) : "f"(f)); return u;
}
__device__ __forceinline__ void mma_tf32(float* c, const uint32_t* a, uint32_t b0, uint32_t b1) {
    asm volatile("mma.sync.aligned.m16n8k8.row.col.f32.tf32.tf32.f32 "
        "{%0,%1,%2,%3}, {%4,%5,%6,%7}, {%8,%9}, {%0,%1,%2,%3};"
        : "+f"(c[0]), "+f"(c[1]), "+f"(c[2]), "+f"(c[3])
        : "r"(a[0]), "r"(a[1]), "r"(a[2]), "r"(a[3]), "r"(b0), "r"(b1));
}

#define AS_LD 36
#define BS_LD 100

// stage one 32-K chunk of A (row stride = ldk floats) and B ([k][96] row-major)
__device__ __forceinline__ void stage_chunk(
    const float* __restrict__ A, int ldk, int kb, int rowblock, int M,
    const float* __restrict__ B,
    uint32_t* As, uint32_t* Bs, int tid)
{
    const float4 z4 = make_float4(0.f, 0.f, 0.f, 0.f);
#pragma unroll
    for (int i = 0; i < 4; i++) {
        int id = tid + 256 * i;
        int r = id >> 3, f4 = id & 7;
        int gr = rowblock + r;
        float4 v = (gr < M) ? __ldg((const float4*)(A + (size_t)gr * ldk + kb) + f4) : z4;
        uint4 u = make_uint4(f2tf(v.x), f2tf(v.y), f2tf(v.z), f2tf(v.w));
        *(uint4*)(&As[r * AS_LD + f4 * 4]) = u;
    }
#pragma unroll
    for (int i = 0; i < 3; i++) {
        int id = tid + 256 * i;
        int r = id / 24, f4 = id % 24;
        float4 v = __ldg((const float4*)(B + (size_t)(kb + r) * 96) + f4);
        uint4 u = make_uint4(f2tf(v.x), f2tf(v.y), f2tf(v.z), f2tf(v.w));
        *(uint4*)(&Bs[r * BS_LD + f4 * 4]) = u;
    }
}

#define MMA_COMPUTE(cacc)                                                       \
    do {                                                                        \
        _Pragma("unroll")                                                       \
        for (int k8 = 0; k8 < 32; k8 += 8) {                                    \
            uint32_t a[2][4];                                                   \
            _Pragma("unroll")                                                   \
            for (int mt = 0; mt < 2; mt++) {                                    \
                int rb = mw * 32 + mt * 16;                                     \
                a[mt][0] = As[(rb + g) * AS_LD + k8 + tig];                     \
                a[mt][1] = As[(rb + g + 8) * AS_LD + k8 + tig];                 \
                a[mt][2] = As[(rb + g) * AS_LD + k8 + tig + 4];                 \
                a[mt][3] = As[(rb + g + 8) * AS_LD + k8 + tig + 4];             \
            }                                                                   \
            _Pragma("unroll")                                                   \
            for (int nt = 0; nt < 6; nt++) {                                    \
                int cb = nw * 48 + nt * 8;                                      \
                uint32_t b0 = Bs[(k8 + tig) * BS_LD + cb + g];                  \
                uint32_t b1 = Bs[(k8 + tig + 4) * BS_LD + cb + g];              \
                mma_tf32(cacc[0][nt], a[0], b0, b1);                            \
                mma_tf32(cacc[1][nt], a[1], b0, b1);                            \
            }                                                                   \
        }                                                                       \
    } while (0)

// ---------------- epilogue store ----------------
#define MMA_STORE(cacc)                                                         \
    do {                                                                        \
        _Pragma("unroll")                                                       \
        for (int mt = 0; mt < 2; mt++) {                                        \
            int r0 = rowblock + mw * 32 + mt * 16 + g;                          \
            int r1 = r0 + 8;                                                    \
            _Pragma("unroll")                                                   \
            for (int nt = 0; nt < 6; nt++) {                                    \
                int colx = nw * 48 + nt * 8 + 2 * tig;                          \
                float bx = __ldg(bias + colx), by = __ldg(bias + colx + 1);     \
                float v0 = fmaxf(cacc[0 + mt][nt][0] + bx, 0.f);                \
                float v1 = fmaxf(cacc[0 + mt][nt][1] + by, 0.f);                \
                float v2 = fmaxf(cacc[0 + mt][nt][2] + bx, 0.f);                \
                float v3 = fmaxf(cacc[0 + mt][nt][3] + by, 0.f);                \
                if (r0 < M) *(float2*)(C + (size_t)r0 * DD + colx) = make_float2(v0, v1); \
                if (r1 < M) *(float2*)(C + (size_t)r1 * DD + colx) = make_float2(v2, v3); \
            }                                                                   \
        }                                                                       \
    } while (0)

// ---------------- lin: h = relu(x @ WfT + bf), K=128 ----------------
__global__ __launch_bounds__(256) void k_lin(
    const float* __restrict__ A, int M,
    const float* __restrict__ Bw, const float* __restrict__ bias,
    float* __restrict__ C)
{
    __shared__ uint32_t As[128 * AS_LD];
    __shared__ uint32_t Bs[32 * BS_LD];
    int tid = threadIdx.x;
    int lane = tid & 31, warp = tid >> 5;
    int g = lane >> 2, tig = lane & 3;
    int mw = warp & 3, nw = warp >> 2;
    int rowblock = blockIdx.x * 128;

    float c[2][6][4];
#pragma unroll
    for (int i = 0; i < 2; i++)
#pragma unroll
        for (int j = 0; j < 6; j++)
#pragma unroll
            for (int q = 0; q < 4; q++) c[i][j][q] = 0.f;

    for (int kb = 0; kb < FF; kb += 32) {
        stage_chunk(A, FF, kb, rowblock, M, Bw + (size_t)kb * 96 - (size_t)kb * 96, As, Bs, tid);
        // note: B pointer passed with kb applied inside stage (B[(kb+r)*96])
        __syncthreads();
        MMA_COMPUTE(c);
        __syncthreads();
    }
    MMA_STORE(c);
}

// ---------------- combine: out = relu(bias + h@root + a0@W0 + a1@W1), K=9x32 -----
__global__ __launch_bounds__(256) void k_combine(
    const float* __restrict__ h, const float* __restrict__ a0,
    const float* __restrict__ a1, int M,
    const float* __restrict__ root, const float* __restrict__ W0,
    const float* __restrict__ W1, const float* __restrict__ bias,
    float* __restrict__ C)
{
    __shared__ uint32_t As[128 * AS_LD];
    __shared__ uint32_t Bs[32 * BS_LD];
    int tid = threadIdx.x;
    int lane = tid & 31, warp = tid >> 5;
    int g = lane >> 2, tig = lane & 3;
    int mw = warp & 3, nw = warp >> 2;
    int rowblock = blockIdx.x * 128;

    float c[2][6][4];
#pragma unroll
    for (int i = 0; i < 2; i++)
#pragma unroll
        for (int j = 0; j < 6; j++)
#pragma unroll
            for (int q = 0; q < 4; q++) c[i][j][q] = 0.f;

    for (int ch = 0; ch < 9; ch++) {
        int s = ch / 3;                      // source index
        int kb = (ch - s * 3) * 32;          // local k offset
        const float* Asrc = (s == 0) ? h : ((s == 1) ? a0 : a1);
        const float* Bsrc = (s == 0) ? root : ((s == 1) ? W0 : W1);
        stage_chunk(Asrc, DD, kb, rowblock, M, Bsrc, As, Bs, tid);
        __syncthreads();
        MMA_COMPUTE(c);
        __syncthreads();
    }
    MMA_STORE(c);
}

// ---------------- launch ----------------
extern "C" void kernel_launch(void* const* d_in, const int* in_sizes, int n_in,
                              void* d_out, int out_size) {
    const float* x    = (const float*)d_in[0];
    const int*   ei   = (const int*)d_in[1];
    const float* attr = (const float*)d_in[2];
    const float* Wf   = (const float*)d_in[3];
    const float* bf   = (const float*)d_in[4];
    const float* W    = (const float*)d_in[5];
    const float* root = (const float*)d_in[6];
    const float* bias = (const float*)d_in[7];
    float* out = (float*)d_out;

    int E = in_sizes[1] / 2;
    int N = in_sizes[0] / FF;
    int N2 = 2 * N;

    void *pA, *pB, *p0, *p1, *pWfT, *pdg, *prp, *pc, *pcol;
    cudaGetSymbolAddress(&pA, g_hA);
    cudaGetSymbolAddress(&pB, g_hB);
    cudaGetSymbolAddress(&p0, g_a0);
    cudaGetSymbolAddress(&p1, g_a1);
    cudaGetSymbolAddress(&pWfT, g_WfT);
    cudaGetSymbolAddress(&pdg, g_deg);
    cudaGetSymbolAddress(&prp, g_rowptr);
    cudaGetSymbolAddress(&pc, g_cur);
    cudaGetSymbolAddress(&pcol, g_col);

    k_prep<<<(N2 + 255) / 256, 256>>>(Wf, (float*)pWfT, (int*)pdg, N2);
    k_hist<<<(E / 2 + 255) / 256, 256>>>(ei, attr, (int*)pdg, E);
    k_scan<<<1, 1024>>>((int*)pdg, (int*)prp, (int*)pc, N2);
    k_fill<<<(E / 2 + 255) / 256, 256>>>(ei, attr, (int*)pc, (int*)pcol, E);

    int mblocks = (N + 127) / 128;
    k_lin<<<mblocks, 256>>>(x, N, (const float*)pWfT, bf, (float*)pA);

    const float* W0 = W;
    const float* W1 = W + DD * DD;
    float* hin = (float*)pA;
    float* hout = (float*)pB;
    for (int it = 0; it < 3; it++) {
        k_agg<<<(N * 32 + 255) / 256, 256>>>(hin, (int*)prp, (int*)pcol,
                                             (float*)p0, (float*)p1, N);
        float* o = (it == 2) ? out : hout;
        k_combine<<<mblocks, 256>>>(hin, (const float*)p0, (const float*)p1, N,
                                    root, W0, W1, bias, o);
        float* t = hin; hin = hout; hout = t;
    }
}

// round 5
// speedup vs baseline: 1.0076x; 1.0076x over previous
#include <cuda_runtime.h>
#include <cuda_fp16.h>
#include <cstdint>

#define NN 50000
#define EE 800000
#define DD 96
#define FF 128

// ---------------- scratch ----------------
__device__ __align__(16) float g_hA[NN * DD];
__device__ __align__(16) float g_hB[NN * DD];
__device__ __align__(16) float g_Troot[NN * DD];        // fp32 root-transformed
__device__ __align__(16) __half g_Tmsg[NN * 192];       // [N][rel0:96 | rel1:96] fp16
__device__ __align__(16) float g_WfT[FF * DD];
__device__ int g_deg[2 * NN];
__device__ int g_cur[2 * NN];
__device__ int g_rowptr[2 * NN + 1];
__device__ int g_col[EE];

// ---------------- prep: zero deg + transpose Wf ----------------
__global__ void k_prep(const float* __restrict__ Wf, float* __restrict__ WfT,
                       int* __restrict__ deg, int N2) {
    int i = blockIdx.x * blockDim.x + threadIdx.x;
    if (i < N2) deg[i] = 0;
    if (i < DD * FF) {
        int d = i >> 7, k = i & 127;
        WfT[k * DD + d] = Wf[i];
    }
}

// ---------------- CSR build ----------------
__global__ void k_hist(const int* __restrict__ ei, const float* __restrict__ attr,
                       int* __restrict__ deg, int E) {
    int e = (blockIdx.x * blockDim.x + threadIdx.x) * 2;
    if (e >= E) return;
    int2 d2 = *(const int2*)(ei + E + e);
    float4 a4 = *(const float4*)(attr + 2 * e);
    atomicAdd(&deg[2 * d2.x + (a4.y > a4.x ? 1 : 0)], 1);
    if (e + 1 < E)
        atomicAdd(&deg[2 * d2.y + (a4.w > a4.z ? 1 : 0)], 1);
}

__global__ void k_scan(const int* __restrict__ deg, int* __restrict__ rowptr,
                       int* __restrict__ cur, int N2) {
    __shared__ int part[1024];
    int tid = threadIdx.x;
    const int CH = (N2 + 1023) / 1024;
    int start = tid * CH;
    int end = start + CH; if (end > N2) end = N2; if (start > N2) start = N2;
    int s = 0;
    for (int i = start; i < end; i++) s += deg[i];
    part[tid] = s;
    __syncthreads();
    for (int off = 1; off < 1024; off <<= 1) {
        int v = (tid >= off) ? part[tid - off] : 0;
        __syncthreads();
        part[tid] += v;
        __syncthreads();
    }
    int excl = (tid == 0) ? 0 : part[tid - 1];
    for (int i = start; i < end; i++) {
        rowptr[i] = excl; cur[i] = excl; excl += deg[i];
    }
    if (tid == 1023) rowptr[N2] = part[1023];
}

__global__ void k_fill(const int* __restrict__ ei, const float* __restrict__ attr,
                       int* __restrict__ cur, int* __restrict__ col, int E) {
    int e = (blockIdx.x * blockDim.x + threadIdx.x) * 2;
    if (e >= E) return;
    int2 s2 = *(const int2*)(ei + e);
    int2 d2 = *(const int2*)(ei + E + e);
    float4 a4 = *(const float4*)(attr + 2 * e);
    {
        int seg = 2 * d2.x + (a4.y > a4.x ? 1 : 0);
        col[atomicAdd(&cur[seg], 1)] = s2.x;
    }
    if (e + 1 < E) {
        int seg = 2 * d2.y + (a4.w > a4.z ? 1 : 0);
        col[atomicAdd(&cur[seg], 1)] = s2.y;
    }
}

// ---------------- tf32 MMA GEMM ----------------
__device__ __forceinline__ uint32_t f2tf(float f) {
    uint32_t u; asm("cvt.rna.tf32.f32 %0, %1;" : "=r"(u) : "f"(f)); return u;
}
__device__ __forceinline__ void mma_tf32(float* c, const uint32_t* a, uint32_t b0, uint32_t b1) {
    asm volatile("mma.sync.aligned.m16n8k8.row.col.f32.tf32.tf32.f32 "
        "{%0,%1,%2,%3}, {%4,%5,%6,%7}, {%8,%9}, {%0,%1,%2,%3};"
        : "+f"(c[0]), "+f"(c[1]), "+f"(c[2]), "+f"(c[3])
        : "r"(a[0]), "r"(a[1]), "r"(a[2]), "r"(a[3]), "r"(b0), "r"(b1));
}

#define AS_LD 36
#define BS_LD 100

// C-paths: blockIdx.y==0 -> fp32 out Cf (ldc=DD, optional bias/relu)
//          blockIdx.y>0  -> fp16 out Ch at column chunk (y-1)*96, row stride 192
__global__ __launch_bounds__(256) void k_gemm(
    const float* __restrict__ A, int M, int K,
    const float* __restrict__ B0, const float* __restrict__ B1, const float* __restrict__ B2,
    float* __restrict__ Cf, __half* __restrict__ Ch,
    const float* __restrict__ bias, int relu)
{
    __shared__ uint32_t As[128 * AS_LD];
    __shared__ uint32_t Bs[32 * BS_LD];
    const float* B = (blockIdx.y == 0) ? B0 : ((blockIdx.y == 1) ? B1 : B2);

    int tid = threadIdx.x;
    int lane = tid & 31;
    int warp = tid >> 5;
    int g = lane >> 2, tig = lane & 3;
    int mw = warp & 3;
    int nw = warp >> 2;
    int rowblock = blockIdx.x * 128;

    int ar[4], af[4], br_[3], bf_[3];
#pragma unroll
    for (int i = 0; i < 4; i++) { int id = tid + 256 * i; ar[i] = id >> 3; af[i] = id & 7; }
#pragma unroll
    for (int i = 0; i < 3; i++) { int id = tid + 256 * i; br_[i] = id / 24; bf_[i] = id % 24; }

    float c[2][6][4];
#pragma unroll
    for (int i = 0; i < 2; i++)
#pragma unroll
        for (int j = 0; j < 6; j++)
#pragma unroll
            for (int q = 0; q < 4; q++) c[i][j][q] = 0.f;

    const float4 z4 = make_float4(0.f, 0.f, 0.f, 0.f);
    float4 a_reg[4], b_reg[3];

#pragma unroll
    for (int i = 0; i < 4; i++) {
        int gr = rowblock + ar[i];
        a_reg[i] = (gr < M) ? __ldg((const float4*)(A + (size_t)gr * K) + af[i]) : z4;
    }
#pragma unroll
    for (int i = 0; i < 3; i++)
        b_reg[i] = __ldg((const float4*)(B + (size_t)br_[i] * 96) + bf_[i]);
#pragma unroll
    for (int i = 0; i < 4; i++) {
        uint4 u = make_uint4(f2tf(a_reg[i].x), f2tf(a_reg[i].y), f2tf(a_reg[i].z), f2tf(a_reg[i].w));
        *(uint4*)(&As[ar[i] * AS_LD + af[i] * 4]) = u;
    }
#pragma unroll
    for (int i = 0; i < 3; i++) {
        uint4 u = make_uint4(f2tf(b_reg[i].x), f2tf(b_reg[i].y), f2tf(b_reg[i].z), f2tf(b_reg[i].w));
        *(uint4*)(&Bs[br_[i] * BS_LD + bf_[i] * 4]) = u;
    }
    __syncthreads();

    for (int kb = 0; kb < K; kb += 32) {
        bool more = (kb + 32 < K);
        if (more) {
#pragma unroll
            for (int i = 0; i < 4; i++) {
                int gr = rowblock + ar[i];
                a_reg[i] = (gr < M) ? __ldg((const float4*)(A + (size_t)gr * K + kb + 32) + af[i]) : z4;
            }
#pragma unroll
            for (int i = 0; i < 3; i++)
                b_reg[i] = __ldg((const float4*)(B + (size_t)(kb + 32 + br_[i]) * 96) + bf_[i]);
        }
#pragma unroll
        for (int k8 = 0; k8 < 32; k8 += 8) {
            uint32_t a[2][4];
#pragma unroll
            for (int mt = 0; mt < 2; mt++) {
                int rb = mw * 32 + mt * 16;
                a[mt][0] = As[(rb + g) * AS_LD + k8 + tig];
                a[mt][1] = As[(rb + g + 8) * AS_LD + k8 + tig];
                a[mt][2] = As[(rb + g) * AS_LD + k8 + tig + 4];
                a[mt][3] = As[(rb + g + 8) * AS_LD + k8 + tig + 4];
            }
#pragma unroll
            for (int nt = 0; nt < 6; nt++) {
                int cb = nw * 48 + nt * 8;
                uint32_t b0 = Bs[(k8 + tig) * BS_LD + cb + g];
                uint32_t b1 = Bs[(k8 + tig + 4) * BS_LD + cb + g];
                mma_tf32(c[0][nt], a[0], b0, b1);
                mma_tf32(c[1][nt], a[1], b0, b1);
            }
        }
        __syncthreads();
        if (more) {
#pragma unroll
            for (int i = 0; i < 4; i++) {
                uint4 u = make_uint4(f2tf(a_reg[i].x), f2tf(a_reg[i].y), f2tf(a_reg[i].z), f2tf(a_reg[i].w));
                *(uint4*)(&As[ar[i] * AS_LD + af[i] * 4]) = u;
            }
#pragma unroll
            for (int i = 0; i < 3; i++) {
                uint4 u = make_uint4(f2tf(b_reg[i].x), f2tf(b_reg[i].y), f2tf(b_reg[i].z), f2tf(b_reg[i].w));
                *(uint4*)(&Bs[br_[i] * BS_LD + bf_[i] * 4]) = u;
            }
            __syncthreads();
        }
    }

    if (blockIdx.y == 0) {
#pragma unroll
        for (int mt = 0; mt < 2; mt++) {
            int r0 = rowblock + mw * 32 + mt * 16 + g;
            int r1 = r0 + 8;
#pragma unroll
            for (int nt = 0; nt < 6; nt++) {
                int colx = nw * 48 + nt * 8 + 2 * tig;
                float bx = 0.f, by = 0.f;
                if (bias) { bx = __ldg(bias + colx); by = __ldg(bias + colx + 1); }
                float v0 = c[mt][nt][0] + bx, v1 = c[mt][nt][1] + by;
                float v2 = c[mt][nt][2] + bx, v3 = c[mt][nt][3] + by;
                if (relu) {
                    v0 = fmaxf(v0, 0.f); v1 = fmaxf(v1, 0.f);
                    v2 = fmaxf(v2, 0.f); v3 = fmaxf(v3, 0.f);
                }
                if (r0 < M) *(float2*)(Cf + (size_t)r0 * DD + colx) = make_float2(v0, v1);
                if (r1 < M) *(float2*)(Cf + (size_t)r1 * DD + colx) = make_float2(v2, v3);
            }
        }
    } else {
        int colchunkH = (blockIdx.y - 1) * 96;
#pragma unroll
        for (int mt = 0; mt < 2; mt++) {
            int r0 = rowblock + mw * 32 + mt * 16 + g;
            int r1 = r0 + 8;
#pragma unroll
            for (int nt = 0; nt < 6; nt++) {
                int colx = nw * 48 + nt * 8 + 2 * tig;
                if (r0 < M)
                    *(__half2*)(Ch + (size_t)r0 * 192 + colchunkH + colx) =
                        __floats2half2_rn(c[mt][nt][0], c[mt][nt][1]);
                if (r1 < M)
                    *(__half2*)(Ch + (size_t)r1 * 192 + colchunkH + colx) =
                        __floats2half2_rn(c[mt][nt][2], c[mt][nt][3]);
            }
        }
    }
}

// ---------------- fused half2 gather + mean + root + bias + relu ----------------
// lane owns dims {2l, 2l+1}; lanes 0..15 additionally own {64+2l, 64+2l+1}
__global__ void k_aggout(const __half* __restrict__ Tmsg, const float* __restrict__ Troot,
                         const int* __restrict__ rowptr, const int* __restrict__ col,
                         const float* __restrict__ bias, float* __restrict__ out, int N) {
    int warpi = (blockIdx.x * blockDim.x + threadIdx.x) >> 5;
    int lane = threadIdx.x & 31;
    if (warpi >= N) return;
    int n = warpi;
    int e00 = __ldg(&rowptr[2 * n]);
    int e01 = __ldg(&rowptr[2 * n + 1]);
    int e11 = __ldg(&rowptr[2 * n + 2]);
    bool hi = (lane < 16);

    float2 x0 = make_float2(0.f, 0.f), x1 = make_float2(0.f, 0.f);   // rel0
    float2 y0 = make_float2(0.f, 0.f), y1 = make_float2(0.f, 0.f);   // rel1

    int e = e00;
    for (; e + 1 < e01; e += 2) {
        const __half2* pa = (const __half2*)(Tmsg + (size_t)__ldg(&col[e])     * 192);
        const __half2* pb = (const __half2*)(Tmsg + (size_t)__ldg(&col[e + 1]) * 192);
        float2 fa = __half22float2(__ldg(pa + lane));
        float2 fb = __half22float2(__ldg(pb + lane));
        x0.x += fa.x + fb.x; x0.y += fa.y + fb.y;
        if (hi) {
            float2 ga = __half22float2(__ldg(pa + 32 + lane));
            float2 gb = __half22float2(__ldg(pb + 32 + lane));
            x1.x += ga.x + gb.x; x1.y += ga.y + gb.y;
        }
    }
    if (e < e01) {
        const __half2* pa = (const __half2*)(Tmsg + (size_t)__ldg(&col[e]) * 192);
        float2 fa = __half22float2(__ldg(pa + lane));
        x0.x += fa.x; x0.y += fa.y;
        if (hi) {
            float2 ga = __half22float2(__ldg(pa + 32 + lane));
            x1.x += ga.x; x1.y += ga.y;
        }
    }
    e = e01;
    for (; e + 1 < e11; e += 2) {
        const __half2* pa = (const __half2*)(Tmsg + (size_t)__ldg(&col[e])     * 192) + 48;
        const __half2* pb = (const __half2*)(Tmsg + (size_t)__ldg(&col[e + 1]) * 192) + 48;
        float2 fa = __half22float2(__ldg(pa + lane));
        float2 fb = __half22float2(__ldg(pb + lane));
        y0.x += fa.x + fb.x; y0.y += fa.y + fb.y;
        if (hi) {
            float2 ga = __half22float2(__ldg(pa + 32 + lane));
            float2 gb = __half22float2(__ldg(pb + 32 + lane));
            y1.x += ga.x + gb.x; y1.y += ga.y + gb.y;
        }
    }
    if (e < e11) {
        const __half2* pa = (const __half2*)(Tmsg + (size_t)__ldg(&col[e]) * 192) + 48;
        float2 fa = __half22float2(__ldg(pa + lane));
        y0.x += fa.x; y0.y += fa.y;
        if (hi) {
            float2 ga = __half22float2(__ldg(pa + 32 + lane));
            y1.x += ga.x; y1.y += ga.y;
        }
    }

    float i0 = 1.f / fmaxf((float)(e01 - e00), 1.f);
    float i1 = 1.f / fmaxf((float)(e11 - e01), 1.f);
    const float* tr = Troot + (size_t)n * DD;
    float* o = out + (size_t)n * DD;
    {
        float2 r = *(const float2*)(tr + 2 * lane);
        float2 b = *(const float2*)(bias + 2 * lane);
        float2 v;
        v.x = fmaxf(b.x + r.x + x0.x * i0 + y0.x * i1, 0.f);
        v.y = fmaxf(b.y + r.y + x0.y * i0 + y0.y * i1, 0.f);
        *(float2*)(o + 2 * lane) = v;
    }
    if (hi) {
        float2 r = *(const float2*)(tr + 64 + 2 * lane);
        float2 b = *(const float2*)(bias + 64 + 2 * lane);
        float2 v;
        v.x = fmaxf(b.x + r.x + x1.x * i0 + y1.x * i1, 0.f);
        v.y = fmaxf(b.y + r.y + x1.y * i0 + y1.y * i1, 0.f);
        *(float2*)(o + 64 + 2 * lane) = v;
    }
}

// ---------------- launch ----------------
extern "C" void kernel_launch(void* const* d_in, const int* in_sizes, int n_in,
                              void* d_out, int out_size) {
    const float* x    = (const float*)d_in[0];
    const int*   ei   = (const int*)d_in[1];
    const float* attr = (const float*)d_in[2];
    const float* Wf   = (const float*)d_in[3];
    const float* bf   = (const float*)d_in[4];
    const float* W    = (const float*)d_in[5];
    const float* root = (const float*)d_in[6];
    const float* bias = (const float*)d_in[7];
    float* out = (float*)d_out;

    int E = in_sizes[1] / 2;
    int N = in_sizes[0] / FF;
    int N2 = 2 * N;

    void *pA, *pB, *pTr, *pTm, *pWfT, *pdg, *prp, *pc, *pcol;
    cudaGetSymbolAddress(&pA, g_hA);
    cudaGetSymbolAddress(&pB, g_hB);
    cudaGetSymbolAddress(&pTr, g_Troot);
    cudaGetSymbolAddress(&pTm, g_Tmsg);
    cudaGetSymbolAddress(&pWfT, g_WfT);
    cudaGetSymbolAddress(&pdg, g_deg);
    cudaGetSymbolAddress(&prp, g_rowptr);
    cudaGetSymbolAddress(&pc, g_cur);
    cudaGetSymbolAddress(&pcol, g_col);

    k_prep<<<(N2 + 255) / 256, 256>>>(Wf, (float*)pWfT, (int*)pdg, N2);
    k_hist<<<(E / 2 + 255) / 256, 256>>>(ei, attr, (int*)pdg, E);
    k_scan<<<1, 1024>>>((int*)pdg, (int*)prp, (int*)pc, N2);
    k_fill<<<(E / 2 + 255) / 256, 256>>>(ei, attr, (int*)pc, (int*)pcol, E);

    int mblocks = (N + 127) / 128;
    // h = relu(x @ WfT + bf)
    k_gemm<<<dim3(mblocks, 1), 256>>>(x, N, FF, (const float*)pWfT, nullptr, nullptr,
                                      (float*)pA, nullptr, bf, 1);

    const float* W0 = W;
    const float* W1 = W + DD * DD;
    float* hin = (float*)pA;
    float* hout = (float*)pB;
    for (int it = 0; it < 3; it++) {
        // Troot = h@root (fp32) ; Tmsg = [h@W0 | h@W1] (fp16)
        k_gemm<<<dim3(mblocks, 3), 256>>>(hin, N, DD, root, W0, W1,
                                          (float*)pTr, (__half*)pTm, nullptr, 0);
        float* o = (it == 2) ? out : hout;
        k_aggout<<<(N * 32 + 255) / 256, 256>>>((const __half*)pTm, (const float*)pTr,
                                                (int*)prp, (int*)pcol, bias, o, N);
        float* t = hin; hin = hout; hout = t;
    }
}

// round 6
// speedup vs baseline: 1.4299x; 1.4191x over previous
#include <cuda_runtime.h>
#include <cstdint>

#define NN 50000
#define EE 800000
#define DD 96
#define FF 128

// ---------------- scratch ----------------
__device__ __align__(16) float g_hA[NN * DD];
__device__ __align__(16) float g_hB[NN * DD];
__device__ __align__(16) float g_T[NN * 3 * DD];   // [N][288]: root | rel0 | rel1
__device__ __align__(16) float g_WfT[FF * DD];
__device__ int g_deg[2 * NN];
__device__ int g_cur[2 * NN];
__device__ int g_rowptr[2 * NN + 1];
__device__ int g_col[EE];
__device__ int g_bpart[256];

// ---------------- prep: zero deg + transpose Wf ----------------
__global__ void k_prep(const float* __restrict__ Wf, float* __restrict__ WfT,
                       int* __restrict__ deg, int N2) {
    int i = blockIdx.x * blockDim.x + threadIdx.x;
    if (i < N2) deg[i] = 0;
    if (i < DD * FF) {
        int d = i >> 7, k = i & 127;
        WfT[k * DD + d] = Wf[i];
    }
}

// ---------------- CSR build ----------------
__global__ void k_hist(const int* __restrict__ ei, const float* __restrict__ attr,
                       int* __restrict__ deg, int E) {
    int e = (blockIdx.x * blockDim.x + threadIdx.x) * 2;
    if (e >= E) return;
    int2 d2 = *(const int2*)(ei + E + e);
    float4 a4 = *(const float4*)(attr + 2 * e);
    atomicAdd(&deg[2 * d2.x + (a4.y > a4.x ? 1 : 0)], 1);
    if (e + 1 < E)
        atomicAdd(&deg[2 * d2.y + (a4.w > a4.z ? 1 : 0)], 1);
}

// --- multiblock coalesced scan: A) block partial sums ---
__global__ __launch_bounds__(1024) void k_scanA(const int* __restrict__ deg,
                                                int* __restrict__ bpart, int N2) {
    __shared__ int red[32];
    int t = threadIdx.x;
    int i = blockIdx.x * 1024 + t;
    int v = (i < N2) ? deg[i] : 0;
#pragma unroll
    for (int o = 16; o; o >>= 1) v += __shfl_down_sync(~0u, v, o);
    if ((t & 31) == 0) red[t >> 5] = v;
    __syncthreads();
    if (t < 32) {
        int s = red[t];
#pragma unroll
        for (int o = 16; o; o >>= 1) s += __shfl_down_sync(~0u, s, o);
        if (t == 0) bpart[blockIdx.x] = s;
    }
}

// --- B) serial scan of ~98 partials (tiny) ---
__global__ void k_scanB(int* __restrict__ bpart, int nb) {
    if (threadIdx.x == 0) {
        int s = 0;
        for (int i = 0; i < nb; i++) { int v = bpart[i]; bpart[i] = s; s += v; }
        bpart[nb] = s;
    }
}

// --- C) per-block exclusive scan + offset; writes rowptr and cur ---
__global__ __launch_bounds__(1024) void k_scanC(const int* __restrict__ deg,
                                                const int* __restrict__ bpart,
                                                int* __restrict__ rowptr,
                                                int* __restrict__ cur, int N2) {
    __shared__ int sm[1024];
    int t = threadIdx.x;
    int i = blockIdx.x * 1024 + t;
    int v = (i < N2) ? deg[i] : 0;
    sm[t] = v;
    __syncthreads();
#pragma unroll
    for (int o = 1; o < 1024; o <<= 1) {
        int u = (t >= o) ? sm[t - o] : 0;
        __syncthreads();
        sm[t] += u;
        __syncthreads();
    }
    int pos = __ldg(&bpart[blockIdx.x]) + sm[t] - v;   // exclusive
    if (i < N2) {
        rowptr[i] = pos;
        cur[i] = pos;
        if (i == N2 - 1) rowptr[N2] = pos + v;
    }
}

__global__ void k_fill(const int* __restrict__ ei, const float* __restrict__ attr,
                       int* __restrict__ cur, int* __restrict__ col, int E) {
    int e = (blockIdx.x * blockDim.x + threadIdx.x) * 2;
    if (e >= E) return;
    int2 s2 = *(const int2*)(ei + e);
    int2 d2 = *(const int2*)(ei + E + e);
    float4 a4 = *(const float4*)(attr + 2 * e);
    {
        int seg = 2 * d2.x + (a4.y > a4.x ? 1 : 0);
        col[atomicAdd(&cur[seg], 1)] = s2.x;
    }
    if (e + 1 < E) {
        int seg = 2 * d2.y + (a4.w > a4.z ? 1 : 0);
        col[atomicAdd(&cur[seg], 1)] = s2.y;
    }
}

// ---------------- tf32 MMA GEMM ----------------
__device__ __forceinline__ uint32_t f2tf(float f) {
    uint32_t u; asm("cvt.rna.tf32.f32 %0, %1;" : "=r"(u) : "f"(f)); return u;
}
__device__ __forceinline__ void mma_tf32(float* c, const uint32_t* a, uint32_t b0, uint32_t b1) {
    asm volatile("mma.sync.aligned.m16n8k8.row.col.f32.tf32.tf32.f32 "
        "{%0,%1,%2,%3}, {%4,%5,%6,%7}, {%8,%9}, {%0,%1,%2,%3};"
        : "+f"(c[0]), "+f"(c[1]), "+f"(c[2]), "+f"(c[3])
        : "r"(a[0]), "r"(a[1]), "r"(a[2]), "r"(a[3]), "r"(b0), "r"(b1));
}

#define AS_LD 36
#define BS_LD 100

__global__ __launch_bounds__(256) void k_gemm(
    const float* __restrict__ A, int M, int K,
    const float* __restrict__ B0, const float* __restrict__ B1, const float* __restrict__ B2,
    float* __restrict__ C, int ldc, const float* __restrict__ bias, int relu)
{
    __shared__ uint32_t As[128 * AS_LD];
    __shared__ uint32_t Bs[32 * BS_LD];
    const float* B = (blockIdx.y == 0) ? B0 : ((blockIdx.y == 1) ? B1 : B2);

    int tid = threadIdx.x;
    int lane = tid & 31;
    int warp = tid >> 5;
    int g = lane >> 2, tig = lane & 3;
    int mw = warp & 3;
    int nw = warp >> 2;
    int rowblock = blockIdx.x * 128;

    int ar[4], af[4], br_[3], bf_[3];
#pragma unroll
    for (int i = 0; i < 4; i++) { int id = tid + 256 * i; ar[i] = id >> 3; af[i] = id & 7; }
#pragma unroll
    for (int i = 0; i < 3; i++) { int id = tid + 256 * i; br_[i] = id / 24; bf_[i] = id % 24; }

    float c[2][6][4];
#pragma unroll
    for (int i = 0; i < 2; i++)
#pragma unroll
        for (int j = 0; j < 6; j++)
#pragma unroll
            for (int q = 0; q < 4; q++) c[i][j][q] = 0.f;

    const float4 z4 = make_float4(0.f, 0.f, 0.f, 0.f);
    float4 a_reg[4], b_reg[3];

#pragma unroll
    for (int i = 0; i < 4; i++) {
        int gr = rowblock + ar[i];
        a_reg[i] = (gr < M) ? __ldg((const float4*)(A + (size_t)gr * K) + af[i]) : z4;
    }
#pragma unroll
    for (int i = 0; i < 3; i++)
        b_reg[i] = __ldg((const float4*)(B + (size_t)br_[i] * 96) + bf_[i]);
#pragma unroll
    for (int i = 0; i < 4; i++) {
        uint4 u = make_uint4(f2tf(a_reg[i].x), f2tf(a_reg[i].y), f2tf(a_reg[i].z), f2tf(a_reg[i].w));
        *(uint4*)(&As[ar[i] * AS_LD + af[i] * 4]) = u;
    }
#pragma unroll
    for (int i = 0; i < 3; i++) {
        uint4 u = make_uint4(f2tf(b_reg[i].x), f2tf(b_reg[i].y), f2tf(b_reg[i].z), f2tf(b_reg[i].w));
        *(uint4*)(&Bs[br_[i] * BS_LD + bf_[i] * 4]) = u;
    }
    __syncthreads();

    for (int kb = 0; kb < K; kb += 32) {
        bool more = (kb + 32 < K);
        if (more) {
#pragma unroll
            for (int i = 0; i < 4; i++) {
                int gr = rowblock + ar[i];
                a_reg[i] = (gr < M) ? __ldg((const float4*)(A + (size_t)gr * K + kb + 32) + af[i]) : z4;
            }
#pragma unroll
            for (int i = 0; i < 3; i++)
                b_reg[i] = __ldg((const float4*)(B + (size_t)(kb + 32 + br_[i]) * 96) + bf_[i]);
        }
#pragma unroll
        for (int k8 = 0; k8 < 32; k8 += 8) {
            uint32_t a[2][4];
#pragma unroll
            for (int mt = 0; mt < 2; mt++) {
                int rb = mw * 32 + mt * 16;
                a[mt][0] = As[(rb + g) * AS_LD + k8 + tig];
                a[mt][1] = As[(rb + g + 8) * AS_LD + k8 + tig];
                a[mt][2] = As[(rb + g) * AS_LD + k8 + tig + 4];
                a[mt][3] = As[(rb + g + 8) * AS_LD + k8 + tig + 4];
            }
#pragma unroll
            for (int nt = 0; nt < 6; nt++) {
                int cb = nw * 48 + nt * 8;
                uint32_t b0 = Bs[(k8 + tig) * BS_LD + cb + g];
                uint32_t b1 = Bs[(k8 + tig + 4) * BS_LD + cb + g];
                mma_tf32(c[0][nt], a[0], b0, b1);
                mma_tf32(c[1][nt], a[1], b0, b1);
            }
        }
        __syncthreads();
        if (more) {
#pragma unroll
            for (int i = 0; i < 4; i++) {
                uint4 u = make_uint4(f2tf(a_reg[i].x), f2tf(a_reg[i].y), f2tf(a_reg[i].z), f2tf(a_reg[i].w));
                *(uint4*)(&As[ar[i] * AS_LD + af[i] * 4]) = u;
            }
#pragma unroll
            for (int i = 0; i < 3; i++) {
                uint4 u = make_uint4(f2tf(b_reg[i].x), f2tf(b_reg[i].y), f2tf(b_reg[i].z), f2tf(b_reg[i].w));
                *(uint4*)(&Bs[br_[i] * BS_LD + bf_[i] * 4]) = u;
            }
            __syncthreads();
        }
    }

    int colchunk = blockIdx.y * 96;
#pragma unroll
    for (int mt = 0; mt < 2; mt++) {
        int r0 = rowblock + mw * 32 + mt * 16 + g;
        int r1 = r0 + 8;
#pragma unroll
        for (int nt = 0; nt < 6; nt++) {
            int col = nw * 48 + nt * 8 + 2 * tig;
            float bx = 0.f, by = 0.f;
            if (bias) { bx = __ldg(bias + col); by = __ldg(bias + col + 1); }
            float v0 = c[mt][nt][0] + bx, v1 = c[mt][nt][1] + by;
            float v2 = c[mt][nt][2] + bx, v3 = c[mt][nt][3] + by;
            if (relu) {
                v0 = fmaxf(v0, 0.f); v1 = fmaxf(v1, 0.f);
                v2 = fmaxf(v2, 0.f); v3 = fmaxf(v3, 0.f);
            }
            if (r0 < M) *(float2*)(C + (size_t)r0 * ldc + colchunk + col) = make_float2(v0, v1);
            if (r1 < M) *(float2*)(C + (size_t)r1 * ldc + colchunk + col) = make_float2(v2, v3);
        }
    }
}

// ---------------- fused float4 gather + mean + root + bias + relu ----------------
// lanes 0..23 each own one 16B chunk of the 384B message; 1 LDG.128 per edge
__global__ void k_aggout(const float* __restrict__ T, const int* __restrict__ rowptr,
                         const int* __restrict__ col, const float* __restrict__ bias,
                         float* __restrict__ out, int N) {
    int warpi = (blockIdx.x * blockDim.x + threadIdx.x) >> 5;
    int lane = threadIdx.x & 31;
    if (warpi >= N) return;
    int n = warpi;
    int e00 = __ldg(&rowptr[2 * n]);
    int e01 = __ldg(&rowptr[2 * n + 1]);
    int e11 = __ldg(&rowptr[2 * n + 2]);
    int cl = (lane < 24) ? lane : 23;   // clamped chunk index (dup addr, HW dedups)

    float4 x = make_float4(0.f, 0.f, 0.f, 0.f);
    float4 y = make_float4(0.f, 0.f, 0.f, 0.f);

    int e = e00;
    for (; e + 3 < e01; e += 4) {
        const float4* p0 = (const float4*)(T + (size_t)__ldg(&col[e])     * 288 + 96);
        const float4* p1 = (const float4*)(T + (size_t)__ldg(&col[e + 1]) * 288 + 96);
        const float4* p2 = (const float4*)(T + (size_t)__ldg(&col[e + 2]) * 288 + 96);
        const float4* p3 = (const float4*)(T + (size_t)__ldg(&col[e + 3]) * 288 + 96);
        float4 v0 = __ldg(p0 + cl), v1 = __ldg(p1 + cl), v2 = __ldg(p2 + cl), v3 = __ldg(p3 + cl);
        x.x += (v0.x + v1.x) + (v2.x + v3.x);
        x.y += (v0.y + v1.y) + (v2.y + v3.y);
        x.z += (v0.z + v1.z) + (v2.z + v3.z);
        x.w += (v0.w + v1.w) + (v2.w + v3.w);
    }
    for (; e < e01; e++) {
        const float4* p = (const float4*)(T + (size_t)__ldg(&col[e]) * 288 + 96);
        float4 v = __ldg(p + cl);
        x.x += v.x; x.y += v.y; x.z += v.z; x.w += v.w;
    }
    e = e01;
    for (; e + 3 < e11; e += 4) {
        const float4* p0 = (const float4*)(T + (size_t)__ldg(&col[e])     * 288 + 192);
        const float4* p1 = (const float4*)(T + (size_t)__ldg(&col[e + 1]) * 288 + 192);
        const float4* p2 = (const float4*)(T + (size_t)__ldg(&col[e + 2]) * 288 + 192);
        const float4* p3 = (const float4*)(T + (size_t)__ldg(&col[e + 3]) * 288 + 192);
        float4 v0 = __ldg(p0 + cl), v1 = __ldg(p1 + cl), v2 = __ldg(p2 + cl), v3 = __ldg(p3 + cl);
        y.x += (v0.x + v1.x) + (v2.x + v3.x);
        y.y += (v0.y + v1.y) + (v2.y + v3.y);
        y.z += (v0.z + v1.z) + (v2.z + v3.z);
        y.w += (v0.w + v1.w) + (v2.w + v3.w);
    }
    for (; e < e11; e++) {
        const float4* p = (const float4*)(T + (size_t)__ldg(&col[e]) * 288 + 192);
        float4 v = __ldg(p + cl);
        y.x += v.x; y.y += v.y; y.z += v.z; y.w += v.w;
    }

    if (lane < 24) {
        float i0 = 1.f / fmaxf((float)(e01 - e00), 1.f);
        float i1 = 1.f / fmaxf((float)(e11 - e01), 1.f);
        float4 r = __ldg((const float4*)(T + (size_t)n * 288) + lane);
        float4 b = __ldg((const float4*)bias + lane);
        float4 o;
        o.x = fmaxf(b.x + r.x + x.x * i0 + y.x * i1, 0.f);
        o.y = fmaxf(b.y + r.y + x.y * i0 + y.y * i1, 0.f);
        o.z = fmaxf(b.z + r.z + x.z * i0 + y.z * i1, 0.f);
        o.w = fmaxf(b.w + r.w + x.w * i0 + y.w * i1, 0.f);
        *((float4*)(out + (size_t)n * DD) + lane) = o;
    }
}

// ---------------- launch ----------------
extern "C" void kernel_launch(void* const* d_in, const int* in_sizes, int n_in,
                              void* d_out, int out_size) {
    const float* x    = (const float*)d_in[0];
    const int*   ei   = (const int*)d_in[1];
    const float* attr = (const float*)d_in[2];
    const float* Wf   = (const float*)d_in[3];
    const float* bf   = (const float*)d_in[4];
    const float* W    = (const float*)d_in[5];
    const float* root = (const float*)d_in[6];
    const float* bias = (const float*)d_in[7];
    float* out = (float*)d_out;

    int E = in_sizes[1] / 2;
    int N = in_sizes[0] / FF;
    int N2 = 2 * N;
    int nb = (N2 + 1023) / 1024;

    void *pA, *pB, *pT, *pWfT, *pdg, *prp, *pc, *pcol, *pbp;
    cudaGetSymbolAddress(&pA, g_hA);
    cudaGetSymbolAddress(&pB, g_hB);
    cudaGetSymbolAddress(&pT, g_T);
    cudaGetSymbolAddress(&pWfT, g_WfT);
    cudaGetSymbolAddress(&pdg, g_deg);
    cudaGetSymbolAddress(&prp, g_rowptr);
    cudaGetSymbolAddress(&pc, g_cur);
    cudaGetSymbolAddress(&pcol, g_col);
    cudaGetSymbolAddress(&pbp, g_bpart);

    k_prep<<<(N2 + 255) / 256, 256>>>(Wf, (float*)pWfT, (int*)pdg, N2);
    k_hist<<<(E / 2 + 255) / 256, 256>>>(ei, attr, (int*)pdg, E);
    k_scanA<<<nb, 1024>>>((int*)pdg, (int*)pbp, N2);
    k_scanB<<<1, 32>>>((int*)pbp, nb);
    k_scanC<<<nb, 1024>>>((int*)pdg, (int*)pbp, (int*)prp, (int*)pc, N2);
    k_fill<<<(E / 2 + 255) / 256, 256>>>(ei, attr, (int*)pc, (int*)pcol, E);

    int mblocks = (N + 127) / 128;
    // h = relu(x @ WfT + bf)
    k_gemm<<<dim3(mblocks, 1), 256>>>(x, N, FF, (const float*)pWfT, nullptr, nullptr,
                                      (float*)pA, DD, bf, 1);

    const float* W0 = W;
    const float* W1 = W + DD * DD;
    float* hin = (float*)pA;
    float* hout = (float*)pB;
    for (int it = 0; it < 3; it++) {
        // T = [h@root | h@W0 | h@W1]
        k_gemm<<<dim3(mblocks, 3), 256>>>(hin, N, DD, root, W0, W1,
                                          (float*)pT, 3 * DD, nullptr, 0);
        float* o = (it == 2) ? out : hout;
        k_aggout<<<(N * 32 + 255) / 256, 256>>>((const float*)pT, (int*)prp, (int*)pcol,
                                                bias, o, N);
        float* t = hin; hin = hout; hout = t;
    }
}